// round 14
// baseline (speedup 1.0000x reference)
#include <cuda_runtime.h>
#include <cuda_fp16.h>
#include <cstdint>

typedef unsigned long long ull;
typedef unsigned int uint;

#define MAXN 100000
#define MAXE 3200000
#define D 256
#define SBLK 1024

// ---------------- scratch ----------------
__device__ float  g_side[(size_t)MAXN * D];
__device__ __half g_half[(size_t)MAXN * D];
__device__ ull    g_epack[MAXE];
__device__ int    g_hist[MAXN];
__device__ int    g_off[MAXN + 1];
__device__ int    g_cur[MAXN];
__device__ uint   g_w1t[D * D];     // W1 as tf32, row-major [j][k]
__device__ uint   g_w2t[D * D];     // W2 as tf32, row-major [j][k]

__device__ __forceinline__ float lrelu(float x) { return x > 0.0f ? x : 0.01f * x; }
__device__ __forceinline__ uint f2tf32(float f) {
    uint u; asm("cvt.rna.tf32.f32 %0, %1;" : "=r"(u) : "f"(f)); return u;
}
__device__ __forceinline__ uint h2u(__half2 h) { return *reinterpret_cast<uint*>(&h); }
__device__ __forceinline__ __half2 u2h(uint u) { return *reinterpret_cast<__half2*>(&u); }

// m16n8k8 tf32 mma, D += A*B  (fastest mma path reachable on plain sm_103 target)
__device__ __forceinline__ void mma8(float* d, const uint* a, const uint* b) {
    asm volatile(
        "mma.sync.aligned.m16n8k8.row.col.f32.tf32.tf32.f32 "
        "{%0,%1,%2,%3}, {%4,%5,%6,%7}, {%8,%9}, {%0,%1,%2,%3};"
        : "+f"(d[0]), "+f"(d[1]), "+f"(d[2]), "+f"(d[3])
        : "r"(a[0]), "r"(a[1]), "r"(a[2]), "r"(a[3]), "r"(b[0]), "r"(b[1]));
}
__device__ __forceinline__ void cpasync16(uint dst, const void* src) {
    asm volatile("cp.async.cg.shared.global [%0], [%1], 16;" :: "r"(dst), "l"(src) : "memory");
}
__device__ __forceinline__ uint smem_u32(const void* p) {
    uint a; asm("{ .reg .u64 t; cvta.to.shared.u64 t, %1; cvt.u32.u64 %0, t; }" : "=r"(a) : "l"(p));
    return a;
}

// ---------------- 0a. fused prep (side stream): convert ego + wprep -------
__global__ void prep_conv_kernel(const float4* __restrict__ ego4,
                                 const float* __restrict__ W1,
                                 const float* __restrict__ W2,
                                 int n4, int cb) {
    if ((int)blockIdx.x < cb) {
        int i = blockIdx.x * 256 + threadIdx.x;
        if (i < n4) {
            float4 v = ego4[i];
            uint2 o;
            o.x = h2u(__floats2half2_rn(v.x, v.y));
            o.y = h2u(__floats2half2_rn(v.z, v.w));
            ((uint2*)g_half)[i] = o;
        }
    } else {
        int i = (blockIdx.x - cb) * 256 + threadIdx.x;   // 65536 elems = 256 blocks
        g_w1t[i] = f2tf32(W1[i]);
        g_w2t[i] = f2tf32(W2[i]);
    }
}

// ---------------- 0b. zero histogram (main stream, before hist) -----------
__global__ void zero_hist_kernel(int n) {
    int i = blockIdx.x * blockDim.x + threadIdx.x;
    if (i < n) g_hist[i] = 0;
}

// ---------------- 1. histogram of edge rows ----------------
__global__ void hist_kernel(const int* __restrict__ rows, int e) {
    int i = blockIdx.x * blockDim.x + threadIdx.x;
    if (i < e) atomicAdd(&g_hist[rows[i]], 1);
}

// ---------------- 2. single-launch scan: redundant-prefix per block -------
// Block b sums hist[0 .. b*1024) (L2-resident, few us even for the last
// block), then scans its own 1024-chunk. No cross-block handshake.
__global__ __launch_bounds__(SBLK) void scan_kernel2(int n) {
    __shared__ int ws[32];
    __shared__ int s_pre;
    int tid = threadIdx.x, lane = tid & 31, w = tid >> 5;
    int base = blockIdx.x * SBLK;

    // --- sum of all hist before this block's chunk ---
    int pre = 0;
    for (int i = tid; i < base; i += SBLK) pre += g_hist[i];
    #pragma unroll
    for (int d = 16; d; d >>= 1) pre += __shfl_down_sync(0xffffffffu, pre, d);
    if (lane == 0) ws[w] = pre;
    __syncthreads();
    if (w == 0) {
        int s = ws[lane];
        #pragma unroll
        for (int d = 16; d; d >>= 1) s += __shfl_down_sync(0xffffffffu, s, d);
        if (lane == 0) s_pre = s;
    }
    __syncthreads();
    int prebase = s_pre;

    // --- inclusive scan of own chunk ---
    int i = base + tid;
    int v = (i < n) ? g_hist[i] : 0;
    int x = v;
    #pragma unroll
    for (int d = 1; d < 32; d <<= 1) {
        int y = __shfl_up_sync(0xffffffffu, x, d);
        if (lane >= d) x += y;
    }
    __syncthreads();                 // ws free for reuse (phase-B reads done)
    if (lane == 31) ws[w] = x;
    __syncthreads();
    if (w == 0) {
        int s = ws[lane];
        #pragma unroll
        for (int d = 1; d < 32; d <<= 1) {
            int y = __shfl_up_sync(0xffffffffu, s, d);
            if (lane >= d) s += y;
        }
        ws[lane] = s;
    }
    __syncthreads();
    int incl = x + prebase + (w > 0 ? ws[w - 1] : 0);
    if (i < n) {
        g_off[i + 1] = incl;
        g_cur[i]     = incl - v;
    }
    if (base == 0 && tid == 0) g_off[0] = 0;
}

// ---------------- 3. scatter edges (packed 8B records) ----------------
__global__ void scatter_kernel(const int* __restrict__ rows, const int* __restrict__ cols,
                               const float* __restrict__ vals, int e) {
    int i = blockIdx.x * blockDim.x + threadIdx.x;
    if (i < e) {
        int r = rows[i];
        ull rec = (ull)(uint)cols[i] | ((ull)__float_as_uint(vals[i]) << 32);
        int p = atomicAdd(&g_cur[r], 1);
        g_epack[p] = rec;
    }
}

// ---------------- 4. CSR SpMM: warp-per-node, warp-staged edge records ------
__global__ __launch_bounds__(128) void spmm_kernel(int n) {
    int node = blockIdx.x * 4 + (threadIdx.x >> 5);
    if (node >= n) return;
    int lane = threadIdx.x & 31;
    const uint4* tab = (const uint4*)g_half;
    int beg = g_off[node], end = g_off[node + 1];
    float a0[8] = {0,0,0,0,0,0,0,0};
    float a1[8] = {0,0,0,0,0,0,0,0};
    float a2[8] = {0,0,0,0,0,0,0,0};
    float a3[8] = {0,0,0,0,0,0,0,0};

    for (int base = beg; base < end; base += 32) {
        int cnt = end - base; if (cnt > 32) cnt = 32;
        uint lo = 0, hi = 0;
        if (lane < cnt) {
            ull rec = g_epack[base + lane];
            lo = (uint)rec; hi = (uint)(rec >> 32);
        }
        int j = 0;
        for (; j + 4 <= cnt; j += 4) {
            uint  c0 = __shfl_sync(0xffffffffu, lo, j);
            uint  c1 = __shfl_sync(0xffffffffu, lo, j + 1);
            uint  c2 = __shfl_sync(0xffffffffu, lo, j + 2);
            uint  c3 = __shfl_sync(0xffffffffu, lo, j + 3);
            float v0 = __uint_as_float(__shfl_sync(0xffffffffu, hi, j));
            float v1 = __uint_as_float(__shfl_sync(0xffffffffu, hi, j + 1));
            float v2 = __uint_as_float(__shfl_sync(0xffffffffu, hi, j + 2));
            float v3 = __uint_as_float(__shfl_sync(0xffffffffu, hi, j + 3));
            uint4 x0 = tab[(size_t)c0 * 32 + lane];
            uint4 x1 = tab[(size_t)c1 * 32 + lane];
            uint4 x2 = tab[(size_t)c2 * 32 + lane];
            uint4 x3 = tab[(size_t)c3 * 32 + lane];
            float2 p;
            p = __half22float2(u2h(x0.x)); a0[0] += v0*p.x; a0[1] += v0*p.y;
            p = __half22float2(u2h(x0.y)); a0[2] += v0*p.x; a0[3] += v0*p.y;
            p = __half22float2(u2h(x0.z)); a0[4] += v0*p.x; a0[5] += v0*p.y;
            p = __half22float2(u2h(x0.w)); a0[6] += v0*p.x; a0[7] += v0*p.y;
            p = __half22float2(u2h(x1.x)); a1[0] += v1*p.x; a1[1] += v1*p.y;
            p = __half22float2(u2h(x1.y)); a1[2] += v1*p.x; a1[3] += v1*p.y;
            p = __half22float2(u2h(x1.z)); a1[4] += v1*p.x; a1[5] += v1*p.y;
            p = __half22float2(u2h(x1.w)); a1[6] += v1*p.x; a1[7] += v1*p.y;
            p = __half22float2(u2h(x2.x)); a2[0] += v2*p.x; a2[1] += v2*p.y;
            p = __half22float2(u2h(x2.y)); a2[2] += v2*p.x; a2[3] += v2*p.y;
            p = __half22float2(u2h(x2.z)); a2[4] += v2*p.x; a2[5] += v2*p.y;
            p = __half22float2(u2h(x2.w)); a2[6] += v2*p.x; a2[7] += v2*p.y;
            p = __half22float2(u2h(x3.x)); a3[0] += v3*p.x; a3[1] += v3*p.y;
            p = __half22float2(u2h(x3.y)); a3[2] += v3*p.x; a3[3] += v3*p.y;
            p = __half22float2(u2h(x3.z)); a3[4] += v3*p.x; a3[5] += v3*p.y;
            p = __half22float2(u2h(x3.w)); a3[6] += v3*p.x; a3[7] += v3*p.y;
        }
        for (; j < cnt; j++) {
            uint  c = __shfl_sync(0xffffffffu, lo, j);
            float v = __uint_as_float(__shfl_sync(0xffffffffu, hi, j));
            uint4 x = tab[(size_t)c * 32 + lane];
            float2 p;
            p = __half22float2(u2h(x.x)); a0[0] += v*p.x; a0[1] += v*p.y;
            p = __half22float2(u2h(x.y)); a0[2] += v*p.x; a0[3] += v*p.y;
            p = __half22float2(u2h(x.z)); a0[4] += v*p.x; a0[5] += v*p.y;
            p = __half22float2(u2h(x.w)); a0[6] += v*p.x; a0[7] += v*p.y;
        }
    }
    float4 o0, o1;
    o0.x = (a0[0]+a1[0]) + (a2[0]+a3[0]);
    o0.y = (a0[1]+a1[1]) + (a2[1]+a3[1]);
    o0.z = (a0[2]+a1[2]) + (a2[2]+a3[2]);
    o0.w = (a0[3]+a1[3]) + (a2[3]+a3[3]);
    o1.x = (a0[4]+a1[4]) + (a2[4]+a3[4]);
    o1.y = (a0[5]+a1[5]) + (a2[5]+a3[5]);
    o1.z = (a0[6]+a1[6]) + (a2[6]+a3[6]);
    o1.w = (a0[7]+a1[7]) + (a2[7]+a3[7]);
    float4* dst = (float4*)(g_side + (size_t)node * D);
    dst[2*lane]     = o0;
    dst[2*lane + 1] = o1;
}

// ---------------- 5. fused dual GEMM, tf32 mma, 2-stage pipeline ----------
#define TBM 128
#define TBN 128
#define TBK 32
#define XSTR 36
#define TILE_F (TBM * XSTR)            // 4608 uints per tile
#define STAGE_F (4 * TILE_F)           // 18432 uints per stage
#define GEMM_SMEM (2 * STAGE_F * 4)    // 147456 B

__global__ __launch_bounds__(256, 1) void gemm_mma_kernel(
    const float* __restrict__ ego,
    const float* __restrict__ b1, const float* __restrict__ b2,
    float* __restrict__ out, int n)
{
    extern __shared__ char smem_raw[];
    uint* sm = (uint*)smem_raw;
    const uint smb = smem_u32(smem_raw);

    const int tid  = threadIdx.x;
    const int lane = tid & 31;
    const int wid  = tid >> 5;
    const int wm   = (wid >> 2) * 64;
    const int wn   = (wid & 3) * 32;
    const int g    = lane >> 2;
    const int c    = lane & 3;

    const int node0 = blockIdx.x * TBM;
    const int jbase = blockIdx.y * TBN;

    const int pm   = tid >> 1;
    const int ph   = tid & 1;

    float acc1[4][4][4];
    float acc2[4][4][4];
    #pragma unroll
    for (int i = 0; i < 4; i++)
        #pragma unroll
        for (int j = 0; j < 4; j++)
            #pragma unroll
            for (int r = 0; r < 4; r++) { acc1[i][j][r] = 0.f; acc2[i][j][r] = 0.f; }

    int xrow = node0 + pm; if (xrow >= n) xrow = n - 1;
    const float4* egoR  = (const float4*)(ego    + (size_t)xrow * D);
    const float4* sideR = (const float4*)(g_side + (size_t)xrow * D);
    const uint* w1src = g_w1t + (size_t)(jbase + pm) * D + ph * 16;
    const uint* w2src = g_w2t + (size_t)(jbase + pm) * D + ph * 16;
    const uint xoff = pm * XSTR + ph * 16;

    #define W_CPASYNC(stage, ck_) do {                                            \
        uint dbase = smb + (((stage) * STAGE_F) + 2 * TILE_F + xoff) * 4;          \
        const uint* s1 = w1src + (ck_) * TBK;                                     \
        const uint* s2 = w2src + (ck_) * TBK;                                     \
        _Pragma("unroll")                                                          \
        for (int i = 0; i < 4; i++) {                                              \
            cpasync16(dbase + i * 16, s1 + i * 4);                                 \
            cpasync16(dbase + TILE_F * 4 + i * 16, s2 + i * 4);                    \
        }                                                                          \
        asm volatile("cp.async.commit_group;" ::: "memory");                       \
    } while (0)

    #define X_LDG(ck_, e4_, s4_) do {                                             \
        int q0 = (ck_) * 8 + ph * 4;                                               \
        _Pragma("unroll")                                                          \
        for (int q = 0; q < 4; q++) { e4_[q] = egoR[q0 + q]; s4_[q] = sideR[q0 + q]; } \
    } while (0)

    #define X_STS(stage, e4_, s4_) do {                                           \
        uint* Xs = sm + (stage) * STAGE_F;                                         \
        uint* Xp = Xs + TILE_F;                                                    \
        _Pragma("unroll")                                                          \
        for (int q = 0; q < 4; q++) {                                              \
            uint4 sv, pv;                                                          \
            sv.x = f2tf32(e4_[q].x + s4_[q].x); sv.y = f2tf32(e4_[q].y + s4_[q].y);\
            sv.z = f2tf32(e4_[q].z + s4_[q].z); sv.w = f2tf32(e4_[q].w + s4_[q].w);\
            pv.x = f2tf32(e4_[q].x * s4_[q].x); pv.y = f2tf32(e4_[q].y * s4_[q].y);\
            pv.z = f2tf32(e4_[q].z * s4_[q].z); pv.w = f2tf32(e4_[q].w * s4_[q].w);\
            *(uint4*)(Xs + xoff + q * 4) = sv;                                     \
            *(uint4*)(Xp + xoff + q * 4) = pv;                                     \
        }                                                                          \
    } while (0)

    {
        float4 e4[4], s4[4];
        W_CPASYNC(0, 0);
        X_LDG(0, e4, s4);
        X_STS(0, e4, s4);
        asm volatile("cp.async.wait_group 0;" ::: "memory");
        __syncthreads();
    }

    for (int ck = 0; ck < D / TBK; ck++) {
        const int st = ck & 1;
        float4 e4[4], s4[4];
        if (ck < 7) {
            X_LDG(ck + 1, e4, s4);
            W_CPASYNC(st ^ 1, ck + 1);
        }
        {
            uint* Xs  = sm + st * STAGE_F;
            uint* Xp  = Xs + TILE_F;
            uint* W1t = Xp + TILE_F;
            uint* W2t = W1t + TILE_F;
            #pragma unroll
            for (int s = 0; s < 4; s++) {
                uint aS[4][4], aP[4][4];
                #pragma unroll
                for (int am = 0; am < 4; am++) {
                    int base = (wm + am * 16 + g) * XSTR + s * 8 + c;
                    aS[am][0] = Xs[base];
                    aS[am][1] = Xs[base + 8 * XSTR];
                    aS[am][2] = Xs[base + 4];
                    aS[am][3] = Xs[base + 8 * XSTR + 4];
                    aP[am][0] = Xp[base];
                    aP[am][1] = Xp[base + 8 * XSTR];
                    aP[am][2] = Xp[base + 4];
                    aP[am][3] = Xp[base + 8 * XSTR + 4];
                }
                uint bW1[4][2], bW2[4][2];
                #pragma unroll
                for (int bn = 0; bn < 4; bn++) {
                    int base = (wn + bn * 8 + g) * XSTR + s * 8 + c;
                    bW1[bn][0] = W1t[base];
                    bW1[bn][1] = W1t[base + 4];
                    bW2[bn][0] = W2t[base];
                    bW2[bn][1] = W2t[base + 4];
                }
                #pragma unroll
                for (int am = 0; am < 4; am++)
                    #pragma unroll
                    for (int bn = 0; bn < 4; bn++) {
                        mma8(acc1[am][bn], aS[am], bW1[bn]);
                        mma8(acc2[am][bn], aP[am], bW2[bn]);
                    }
            }
        }
        if (ck < 7) {
            X_STS(st ^ 1, e4, s4);
            asm volatile("cp.async.wait_group 0;" ::: "memory");
        }
        __syncthreads();
    }

    #pragma unroll
    for (int bn = 0; bn < 4; bn++) {
        int col = jbase + wn + bn * 8 + c * 2;
        float2 bb1 = *(const float2*)(b1 + col);
        float2 bb2 = *(const float2*)(b2 + col);
        #pragma unroll
        for (int am = 0; am < 4; am++) {
            int r0 = node0 + wm + am * 16 + g;
            int r1 = r0 + 8;
            if (r0 < n) {
                float2 o;
                o.x = lrelu(acc1[am][bn][0] + bb1.x) + lrelu(acc2[am][bn][0] + bb2.x);
                o.y = lrelu(acc1[am][bn][1] + bb1.y) + lrelu(acc2[am][bn][1] + bb2.y);
                *(float2*)(out + (size_t)r0 * D + col) = o;
            }
            if (r1 < n) {
                float2 o;
                o.x = lrelu(acc1[am][bn][2] + bb1.x) + lrelu(acc2[am][bn][2] + bb2.x);
                o.y = lrelu(acc1[am][bn][3] + bb1.y) + lrelu(acc2[am][bn][3] + bb2.y);
                *(float2*)(out + (size_t)r1 * D + col) = o;
            }
        }
    }
}

// ---------------- launch ----------------
extern "C" void kernel_launch(void* const* d_in, const int* in_sizes, int n_in,
                              void* d_out, int out_size) {
    const float* ego   = (const float*)d_in[0];
    const float* evals = (const float*)d_in[1];
    const float* W1    = (const float*)d_in[2];
    const float* b1    = (const float*)d_in[3];
    const float* W2    = (const float*)d_in[4];
    const float* b2    = (const float*)d_in[5];
    const int*   erows = (const int*)d_in[6];
    const int*   ecols = (const int*)d_in[7];
    float* out = (float*)d_out;

    int N = in_sizes[0] / D;
    int E = in_sizes[1];
    if (N > MAXN) N = MAXN;
    if (E > MAXE) E = MAXE;

    static cudaStream_t s2 = 0;
    static cudaEvent_t evA = 0, evB = 0;
    static bool init = false;
    if (!init) {
        cudaFuncSetAttribute(gemm_mma_kernel, cudaFuncAttributeMaxDynamicSharedMemorySize, GEMM_SMEM);
        cudaStreamCreateWithFlags(&s2, cudaStreamNonBlocking);
        cudaEventCreateWithFlags(&evA, cudaEventDisableTiming);
        cudaEventCreateWithFlags(&evB, cudaEventDisableTiming);
        init = true;
    }

    int n4 = N * (D / 4);
    int cb = (n4 + 255) / 256;
    int nscan = (N + SBLK - 1) / SBLK;

    // fork: prep (ego->fp16, W->tf32) runs parallel to the edge pipeline
    cudaEventRecord(evA, 0);
    cudaStreamWaitEvent(s2, evA, 0);
    prep_conv_kernel<<<cb + 256, 256, 0, s2>>>((const float4*)ego, W1, W2, n4, cb);
    cudaEventRecord(evB, s2);

    zero_hist_kernel<<<(N + 255) / 256, 256>>>(N);
    hist_kernel<<<(E + 255) / 256, 256>>>(erows, E);
    scan_kernel2<<<nscan, SBLK>>>(N);
    scatter_kernel<<<(E + 255) / 256, 256>>>(erows, ecols, evals, E);

    // join: spmm needs g_half (+ CSR); gemm additionally needs g_w1t/g_w2t
    cudaStreamWaitEvent(0, evB, 0);
    spmm_kernel<<<(N + 3) / 4, 128>>>(N);
    dim3 ggrid((N + TBM - 1) / TBM, D / TBN);
    gemm_mma_kernel<<<ggrid, 256, GEMM_SMEM>>>(ego, b1, b2, out, N);
}

// round 15
// speedup vs baseline: 1.4112x; 1.4112x over previous
#include <cuda_runtime.h>
#include <cuda_fp16.h>
#include <cstdint>

typedef unsigned long long ull;
typedef unsigned int uint;

#define MAXN 100000
#define MAXE 3200000
#define D 256
#define SBLK 1024

// ---------------- scratch ----------------
__device__ float  g_side[(size_t)MAXN * D];
__device__ __half g_half[(size_t)MAXN * D];
__device__ ull    g_epack[MAXE];
__device__ int    g_hist[MAXN];
__device__ int    g_off[MAXN + 1];
__device__ int    g_cur[MAXN];
__device__ uint   g_w1t[D * D];     // W1 as tf32, row-major [j][k]
__device__ uint   g_w2t[D * D];     // W2 as tf32, row-major [j][k]

__device__ __forceinline__ float lrelu(float x) { return x > 0.0f ? x : 0.01f * x; }
__device__ __forceinline__ uint f2tf32(float f) {
    uint u; asm("cvt.rna.tf32.f32 %0, %1;" : "=r"(u) : "f"(f)); return u;
}
__device__ __forceinline__ uint h2u(__half2 h) { return *reinterpret_cast<uint*>(&h); }
__device__ __forceinline__ __half2 u2h(uint u) { return *reinterpret_cast<__half2*>(&u); }

// m16n8k8 tf32 mma, D += A*B  (fastest mma path reachable on plain sm_103 target)
__device__ __forceinline__ void mma8(float* d, const uint* a, const uint* b) {
    asm volatile(
        "mma.sync.aligned.m16n8k8.row.col.f32.tf32.tf32.f32 "
        "{%0,%1,%2,%3}, {%4,%5,%6,%7}, {%8,%9}, {%0,%1,%2,%3};"
        : "+f"(d[0]), "+f"(d[1]), "+f"(d[2]), "+f"(d[3])
        : "r"(a[0]), "r"(a[1]), "r"(a[2]), "r"(a[3]), "r"(b[0]), "r"(b[1]));
}
__device__ __forceinline__ void cpasync16(uint dst, const void* src) {
    asm volatile("cp.async.cg.shared.global [%0], [%1], 16;" :: "r"(dst), "l"(src) : "memory");
}
__device__ __forceinline__ uint smem_u32(const void* p) {
    uint a; asm("{ .reg .u64 t; cvta.to.shared.u64 t, %1; cvt.u32.u64 %0, t; }" : "=r"(a) : "l"(p));
    return a;
}

// ---------------- 0. zero histogram ----------------
__global__ void zero_hist_kernel(int n) {
    int i = blockIdx.x * blockDim.x + threadIdx.x;
    if (i < n) g_hist[i] = 0;
}

// ---------------- 1. fused: histogram + ego->fp16 convert + W->tf32 -------
// Independent work co-scheduled in one grid (capture-safe overlap; streams
// under graph capture regressed badly in R14).
__global__ void histconv_kernel(const int* __restrict__ rows, int e, int hb,
                                const float4* __restrict__ ego4, int n4, int cb,
                                const float* __restrict__ W1,
                                const float* __restrict__ W2) {
    int b = blockIdx.x;
    if (b < hb) {
        int i = b * 256 + threadIdx.x;
        if (i < e) atomicAdd(&g_hist[rows[i]], 1);
    } else if (b < hb + cb) {
        int i = (b - hb) * 256 + threadIdx.x;
        if (i < n4) {
            float4 v = ego4[i];
            uint2 o;
            o.x = h2u(__floats2half2_rn(v.x, v.y));
            o.y = h2u(__floats2half2_rn(v.z, v.w));
            ((uint2*)g_half)[i] = o;
        }
    } else {
        int i = (b - hb - cb) * 256 + threadIdx.x;   // 65536 elems = 256 blocks
        g_w1t[i] = f2tf32(W1[i]);
        g_w2t[i] = f2tf32(W2[i]);
    }
}

// ---------------- 2. single-launch scan: redundant-prefix per block -------
__global__ __launch_bounds__(SBLK) void scan_kernel2(int n) {
    __shared__ int ws[32];
    __shared__ int s_pre;
    int tid = threadIdx.x, lane = tid & 31, w = tid >> 5;
    int base = blockIdx.x * SBLK;

    int pre = 0;
    for (int i = tid; i < base; i += SBLK) pre += g_hist[i];
    #pragma unroll
    for (int d = 16; d; d >>= 1) pre += __shfl_down_sync(0xffffffffu, pre, d);
    if (lane == 0) ws[w] = pre;
    __syncthreads();
    if (w == 0) {
        int s = ws[lane];
        #pragma unroll
        for (int d = 16; d; d >>= 1) s += __shfl_down_sync(0xffffffffu, s, d);
        if (lane == 0) s_pre = s;
    }
    __syncthreads();
    int prebase = s_pre;

    int i = base + tid;
    int v = (i < n) ? g_hist[i] : 0;
    int x = v;
    #pragma unroll
    for (int d = 1; d < 32; d <<= 1) {
        int y = __shfl_up_sync(0xffffffffu, x, d);
        if (lane >= d) x += y;
    }
    __syncthreads();
    if (lane == 31) ws[w] = x;
    __syncthreads();
    if (w == 0) {
        int s = ws[lane];
        #pragma unroll
        for (int d = 1; d < 32; d <<= 1) {
            int y = __shfl_up_sync(0xffffffffu, s, d);
            if (lane >= d) s += y;
        }
        ws[lane] = s;
    }
    __syncthreads();
    int incl = x + prebase + (w > 0 ? ws[w - 1] : 0);
    if (i < n) {
        g_off[i + 1] = incl;
        g_cur[i]     = incl - v;
    }
    if (base == 0 && tid == 0) g_off[0] = 0;
}

// ---------------- 3. scatter edges (packed 8B records) ----------------
__global__ void scatter_kernel(const int* __restrict__ rows, const int* __restrict__ cols,
                               const float* __restrict__ vals, int e) {
    int i = blockIdx.x * blockDim.x + threadIdx.x;
    if (i < e) {
        int r = rows[i];
        ull rec = (ull)(uint)cols[i] | ((ull)__float_as_uint(vals[i]) << 32);
        int p = atomicAdd(&g_cur[r], 1);
        g_epack[p] = rec;
    }
}

// ---------------- 4. CSR SpMM: warp-per-node, warp-staged edge records ------
__global__ __launch_bounds__(128) void spmm_kernel(int n) {
    int node = blockIdx.x * 4 + (threadIdx.x >> 5);
    if (node >= n) return;
    int lane = threadIdx.x & 31;
    const uint4* tab = (const uint4*)g_half;
    int beg = g_off[node], end = g_off[node + 1];
    float a0[8] = {0,0,0,0,0,0,0,0};
    float a1[8] = {0,0,0,0,0,0,0,0};
    float a2[8] = {0,0,0,0,0,0,0,0};
    float a3[8] = {0,0,0,0,0,0,0,0};

    for (int base = beg; base < end; base += 32) {
        int cnt = end - base; if (cnt > 32) cnt = 32;
        uint lo = 0, hi = 0;
        if (lane < cnt) {
            ull rec = g_epack[base + lane];
            lo = (uint)rec; hi = (uint)(rec >> 32);
        }
        int j = 0;
        for (; j + 4 <= cnt; j += 4) {
            uint  c0 = __shfl_sync(0xffffffffu, lo, j);
            uint  c1 = __shfl_sync(0xffffffffu, lo, j + 1);
            uint  c2 = __shfl_sync(0xffffffffu, lo, j + 2);
            uint  c3 = __shfl_sync(0xffffffffu, lo, j + 3);
            float v0 = __uint_as_float(__shfl_sync(0xffffffffu, hi, j));
            float v1 = __uint_as_float(__shfl_sync(0xffffffffu, hi, j + 1));
            float v2 = __uint_as_float(__shfl_sync(0xffffffffu, hi, j + 2));
            float v3 = __uint_as_float(__shfl_sync(0xffffffffu, hi, j + 3));
            uint4 x0 = tab[(size_t)c0 * 32 + lane];
            uint4 x1 = tab[(size_t)c1 * 32 + lane];
            uint4 x2 = tab[(size_t)c2 * 32 + lane];
            uint4 x3 = tab[(size_t)c3 * 32 + lane];
            float2 p;
            p = __half22float2(u2h(x0.x)); a0[0] += v0*p.x; a0[1] += v0*p.y;
            p = __half22float2(u2h(x0.y)); a0[2] += v0*p.x; a0[3] += v0*p.y;
            p = __half22float2(u2h(x0.z)); a0[4] += v0*p.x; a0[5] += v0*p.y;
            p = __half22float2(u2h(x0.w)); a0[6] += v0*p.x; a0[7] += v0*p.y;
            p = __half22float2(u2h(x1.x)); a1[0] += v1*p.x; a1[1] += v1*p.y;
            p = __half22float2(u2h(x1.y)); a1[2] += v1*p.x; a1[3] += v1*p.y;
            p = __half22float2(u2h(x1.z)); a1[4] += v1*p.x; a1[5] += v1*p.y;
            p = __half22float2(u2h(x1.w)); a1[6] += v1*p.x; a1[7] += v1*p.y;
            p = __half22float2(u2h(x2.x)); a2[0] += v2*p.x; a2[1] += v2*p.y;
            p = __half22float2(u2h(x2.y)); a2[2] += v2*p.x; a2[3] += v2*p.y;
            p = __half22float2(u2h(x2.z)); a2[4] += v2*p.x; a2[5] += v2*p.y;
            p = __half22float2(u2h(x2.w)); a2[6] += v2*p.x; a2[7] += v2*p.y;
            p = __half22float2(u2h(x3.x)); a3[0] += v3*p.x; a3[1] += v3*p.y;
            p = __half22float2(u2h(x3.y)); a3[2] += v3*p.x; a3[3] += v3*p.y;
            p = __half22float2(u2h(x3.z)); a3[4] += v3*p.x; a3[5] += v3*p.y;
            p = __half22float2(u2h(x3.w)); a3[6] += v3*p.x; a3[7] += v3*p.y;
        }
        for (; j < cnt; j++) {
            uint  c = __shfl_sync(0xffffffffu, lo, j);
            float v = __uint_as_float(__shfl_sync(0xffffffffu, hi, j));
            uint4 x = tab[(size_t)c * 32 + lane];
            float2 p;
            p = __half22float2(u2h(x.x)); a0[0] += v*p.x; a0[1] += v*p.y;
            p = __half22float2(u2h(x.y)); a0[2] += v*p.x; a0[3] += v*p.y;
            p = __half22float2(u2h(x.z)); a0[4] += v*p.x; a0[5] += v*p.y;
            p = __half22float2(u2h(x.w)); a0[6] += v*p.x; a0[7] += v*p.y;
        }
    }
    float4 o0, o1;
    o0.x = (a0[0]+a1[0]) + (a2[0]+a3[0]);
    o0.y = (a0[1]+a1[1]) + (a2[1]+a3[1]);
    o0.z = (a0[2]+a1[2]) + (a2[2]+a3[2]);
    o0.w = (a0[3]+a1[3]) + (a2[3]+a3[3]);
    o1.x = (a0[4]+a1[4]) + (a2[4]+a3[4]);
    o1.y = (a0[5]+a1[5]) + (a2[5]+a3[5]);
    o1.z = (a0[6]+a1[6]) + (a2[6]+a3[6]);
    o1.w = (a0[7]+a1[7]) + (a2[7]+a3[7]);
    float4* dst = (float4*)(g_side + (size_t)node * D);
    dst[2*lane]     = o0;
    dst[2*lane + 1] = o1;
}

// ---------------- 5. fused dual GEMM, tf32 mma, 2-stage pipeline ----------
#define TBM 128
#define TBN 128
#define TBK 32
#define XSTR 36
#define TILE_F (TBM * XSTR)            // 4608 uints per tile
#define STAGE_F (4 * TILE_F)           // 18432 uints per stage
#define GEMM_SMEM (2 * STAGE_F * 4)    // 147456 B

__global__ __launch_bounds__(256, 1) void gemm_mma_kernel(
    const float* __restrict__ ego,
    const float* __restrict__ b1, const float* __restrict__ b2,
    float* __restrict__ out, int n)
{
    extern __shared__ char smem_raw[];
    uint* sm = (uint*)smem_raw;
    const uint smb = smem_u32(smem_raw);

    const int tid  = threadIdx.x;
    const int lane = tid & 31;
    const int wid  = tid >> 5;
    const int wm   = (wid >> 2) * 64;
    const int wn   = (wid & 3) * 32;
    const int g    = lane >> 2;
    const int c    = lane & 3;

    const int node0 = blockIdx.x * TBM;
    const int jbase = blockIdx.y * TBN;

    const int pm   = tid >> 1;
    const int ph   = tid & 1;

    float acc1[4][4][4];
    float acc2[4][4][4];
    #pragma unroll
    for (int i = 0; i < 4; i++)
        #pragma unroll
        for (int j = 0; j < 4; j++)
            #pragma unroll
            for (int r = 0; r < 4; r++) { acc1[i][j][r] = 0.f; acc2[i][j][r] = 0.f; }

    int xrow = node0 + pm; if (xrow >= n) xrow = n - 1;
    const float4* egoR  = (const float4*)(ego    + (size_t)xrow * D);
    const float4* sideR = (const float4*)(g_side + (size_t)xrow * D);
    const uint* w1src = g_w1t + (size_t)(jbase + pm) * D + ph * 16;
    const uint* w2src = g_w2t + (size_t)(jbase + pm) * D + ph * 16;
    const uint xoff = pm * XSTR + ph * 16;

    #define W_CPASYNC(stage, ck_) do {                                            \
        uint dbase = smb + (((stage) * STAGE_F) + 2 * TILE_F + xoff) * 4;          \
        const uint* s1 = w1src + (ck_) * TBK;                                     \
        const uint* s2 = w2src + (ck_) * TBK;                                     \
        _Pragma("unroll")                                                          \
        for (int i = 0; i < 4; i++) {                                              \
            cpasync16(dbase + i * 16, s1 + i * 4);                                 \
            cpasync16(dbase + TILE_F * 4 + i * 16, s2 + i * 4);                    \
        }                                                                          \
        asm volatile("cp.async.commit_group;" ::: "memory");                       \
    } while (0)

    #define X_LDG(ck_, e4_, s4_) do {                                             \
        int q0 = (ck_) * 8 + ph * 4;                                               \
        _Pragma("unroll")                                                          \
        for (int q = 0; q < 4; q++) { e4_[q] = egoR[q0 + q]; s4_[q] = sideR[q0 + q]; } \
    } while (0)

    #define X_STS(stage, e4_, s4_) do {                                           \
        uint* Xs = sm + (stage) * STAGE_F;                                         \
        uint* Xp = Xs + TILE_F;                                                    \
        _Pragma("unroll")                                                          \
        for (int q = 0; q < 4; q++) {                                              \
            uint4 sv, pv;                                                          \
            sv.x = f2tf32(e4_[q].x + s4_[q].x); sv.y = f2tf32(e4_[q].y + s4_[q].y);\
            sv.z = f2tf32(e4_[q].z + s4_[q].z); sv.w = f2tf32(e4_[q].w + s4_[q].w);\
            pv.x = f2tf32(e4_[q].x * s4_[q].x); pv.y = f2tf32(e4_[q].y * s4_[q].y);\
            pv.z = f2tf32(e4_[q].z * s4_[q].z); pv.w = f2tf32(e4_[q].w * s4_[q].w);\
            *(uint4*)(Xs + xoff + q * 4) = sv;                                     \
            *(uint4*)(Xp + xoff + q * 4) = pv;                                     \
        }                                                                          \
    } while (0)

    {
        float4 e4[4], s4[4];
        W_CPASYNC(0, 0);
        X_LDG(0, e4, s4);
        X_STS(0, e4, s4);
        asm volatile("cp.async.wait_group 0;" ::: "memory");
        __syncthreads();
    }

    for (int ck = 0; ck < D / TBK; ck++) {
        const int st = ck & 1;
        float4 e4[4], s4[4];
        if (ck < 7) {
            X_LDG(ck + 1, e4, s4);
            W_CPASYNC(st ^ 1, ck + 1);
        }
        {
            uint* Xs  = sm + st * STAGE_F;
            uint* Xp  = Xs + TILE_F;
            uint* W1t = Xp + TILE_F;
            uint* W2t = W1t + TILE_F;
            #pragma unroll
            for (int s = 0; s < 4; s++) {
                uint aS[4][4], aP[4][4];
                #pragma unroll
                for (int am = 0; am < 4; am++) {
                    int base = (wm + am * 16 + g) * XSTR + s * 8 + c;
                    aS[am][0] = Xs[base];
                    aS[am][1] = Xs[base + 8 * XSTR];
                    aS[am][2] = Xs[base + 4];
                    aS[am][3] = Xs[base + 8 * XSTR + 4];
                    aP[am][0] = Xp[base];
                    aP[am][1] = Xp[base + 8 * XSTR];
                    aP[am][2] = Xp[base + 4];
                    aP[am][3] = Xp[base + 8 * XSTR + 4];
                }
                uint bW1[4][2], bW2[4][2];
                #pragma unroll
                for (int bn = 0; bn < 4; bn++) {
                    int base = (wn + bn * 8 + g) * XSTR + s * 8 + c;
                    bW1[bn][0] = W1t[base];
                    bW1[bn][1] = W1t[base + 4];
                    bW2[bn][0] = W2t[base];
                    bW2[bn][1] = W2t[base + 4];
                }
                #pragma unroll
                for (int am = 0; am < 4; am++)
                    #pragma unroll
                    for (int bn = 0; bn < 4; bn++) {
                        mma8(acc1[am][bn], aS[am], bW1[bn]);
                        mma8(acc2[am][bn], aP[am], bW2[bn]);
                    }
            }
        }
        if (ck < 7) {
            X_STS(st ^ 1, e4, s4);
            asm volatile("cp.async.wait_group 0;" ::: "memory");
        }
        __syncthreads();
    }

    #pragma unroll
    for (int bn = 0; bn < 4; bn++) {
        int col = jbase + wn + bn * 8 + c * 2;
        float2 bb1 = *(const float2*)(b1 + col);
        float2 bb2 = *(const float2*)(b2 + col);
        #pragma unroll
        for (int am = 0; am < 4; am++) {
            int r0 = node0 + wm + am * 16 + g;
            int r1 = r0 + 8;
            if (r0 < n) {
                float2 o;
                o.x = lrelu(acc1[am][bn][0] + bb1.x) + lrelu(acc2[am][bn][0] + bb2.x);
                o.y = lrelu(acc1[am][bn][1] + bb1.y) + lrelu(acc2[am][bn][1] + bb2.y);
                *(float2*)(out + (size_t)r0 * D + col) = o;
            }
            if (r1 < n) {
                float2 o;
                o.x = lrelu(acc1[am][bn][2] + bb1.x) + lrelu(acc2[am][bn][2] + bb2.x);
                o.y = lrelu(acc1[am][bn][3] + bb1.y) + lrelu(acc2[am][bn][3] + bb2.y);
                *(float2*)(out + (size_t)r1 * D + col) = o;
            }
        }
    }
}

// ---------------- launch ----------------
extern "C" void kernel_launch(void* const* d_in, const int* in_sizes, int n_in,
                              void* d_out, int out_size) {
    const float* ego   = (const float*)d_in[0];
    const float* evals = (const float*)d_in[1];
    const float* W1    = (const float*)d_in[2];
    const float* b1    = (const float*)d_in[3];
    const float* W2    = (const float*)d_in[4];
    const float* b2    = (const float*)d_in[5];
    const int*   erows = (const int*)d_in[6];
    const int*   ecols = (const int*)d_in[7];
    float* out = (float*)d_out;

    int N = in_sizes[0] / D;
    int E = in_sizes[1];
    if (N > MAXN) N = MAXN;
    if (E > MAXE) E = MAXE;

    static bool init = false;
    if (!init) {
        cudaFuncSetAttribute(gemm_mma_kernel, cudaFuncAttributeMaxDynamicSharedMemorySize, GEMM_SMEM);
        init = true;
    }

    int n4 = N * (D / 4);
    int hb = (E + 255) / 256;
    int cb = (n4 + 255) / 256;
    int nscan = (N + SBLK - 1) / SBLK;

    zero_hist_kernel<<<(N + 255) / 256, 256>>>(N);
    histconv_kernel<<<hb + cb + 256, 256>>>(erows, E, hb, (const float4*)ego, n4, cb, W1, W2);
    scan_kernel2<<<nscan, SBLK>>>(N);
    scatter_kernel<<<(E + 255) / 256, 256>>>(erows, ecols, evals, E);
    spmm_kernel<<<(N + 3) / 4, 128>>>(N);
    dim3 ggrid((N + TBM - 1) / TBM, D / TBN);
    gemm_mma_kernel<<<ggrid, 256, GEMM_SMEM>>>(ego, b1, b2, out, N);
}